// round 1
// baseline (speedup 1.0000x reference)
#include <cuda_runtime.h>
#include <cstdint>

// ---------------------------------------------------------------------------
// Problem constants (fixed by the reference):
//   B=32, S=1024, V=300, PRETRAIN=300, FLAG=16, ROLE_D=200
//   out[(b*S+s)*V + v] = sum_k proj[b,s,k] * roles[b,v,k], col v==1 zeroed
//   proj[b,s,k] = sum_d concat(pre, wid)[b,s,d] * matrix[d,k]
// ---------------------------------------------------------------------------

namespace {
constexpr int ROLE_D   = 200;
constexpr int PRETRAIN = 300;
constexpr int FLAG     = 16;
constexpr int KQ       = PRETRAIN + FLAG;   // 316
constexpr int SEQ_S    = 1024;

constexpr int TS   = 128;   // row tile
constexpr int TN   = 128;   // col tile
constexpr int KC   = 8;     // k chunk
constexpr int SSTR = 132;   // smem row stride (conflict-free transpose, 16B-aligned)
}

// Scratch for the projection (allocation-free rule -> static __device__ array)
__device__ float g_proj[32768 * ROLE_D];

// ===========================================================================
// GEMM1: g_proj[M,200] = concat(pre[M,300], wid[M,16]) @ mat[316,200]
// ===========================================================================
__global__ __launch_bounds__(256, 2) void proj_kernel(
    const float* __restrict__ pre,
    const float* __restrict__ wid,
    const float* __restrict__ mat)
{
    __shared__ float As[KC][SSTR];   // [k][row]
    __shared__ float Bs[KC][SSTR];   // [k][col]

    const int t  = threadIdx.x;
    const int tx = t & 15;           // col group
    const int ty = t >> 4;           // row group
    const int m0 = blockIdx.y * TS;
    const int n0 = blockIdx.x * TN;

    // A loader: each thread fetches one float4 along k, stores transposed
    const int arow = t >> 1;                 // 0..127
    const int akq  = (t & 1) << 2;           // 0 or 4
    // B loader: direct copy (mat is [k][n], n contiguous)
    const int bk = t >> 5;                   // 0..7
    const int bn = (t & 31) << 2;            // 0..124

    float acc[8][8] = {};

    const int nchunks = (KQ + KC - 1) / KC;  // 40 (last chunk zero-padded)
    for (int c = 0; c < nchunks; ++c) {
        const int k0 = c * KC;
        // --- load A tile (virtual concat; 300 & 316 are float4-aligned) ---
        {
            const int k   = k0 + akq;
            const int row = m0 + arow;
            float4 v = make_float4(0.f, 0.f, 0.f, 0.f);
            if (k < PRETRAIN) {
                v = *(const float4*)(pre + (size_t)row * PRETRAIN + k);
            } else if (k < KQ) {
                v = *(const float4*)(wid + (size_t)row * FLAG + (k - PRETRAIN));
            }
            As[akq + 0][arow] = v.x;
            As[akq + 1][arow] = v.y;
            As[akq + 2][arow] = v.z;
            As[akq + 3][arow] = v.w;
        }
        // --- load B tile ---
        {
            const int k = k0 + bk;
            const int n = n0 + bn;
            float4 v = make_float4(0.f, 0.f, 0.f, 0.f);
            if (k < KQ && n < ROLE_D)
                v = *(const float4*)(mat + (size_t)k * ROLE_D + n);
            *(float4*)&Bs[bk][bn] = v;
        }
        __syncthreads();

#pragma unroll
        for (int k = 0; k < KC; ++k) {
            const float4 a0 = *(const float4*)&As[k][ty << 2];
            const float4 a1 = *(const float4*)&As[k][64 + (ty << 2)];
            const float4 b0 = *(const float4*)&Bs[k][tx << 2];
            const float4 b1 = *(const float4*)&Bs[k][64 + (tx << 2)];
            const float a[8] = {a0.x, a0.y, a0.z, a0.w, a1.x, a1.y, a1.z, a1.w};
            const float b[8] = {b0.x, b0.y, b0.z, b0.w, b1.x, b1.y, b1.z, b1.w};
#pragma unroll
            for (int i = 0; i < 8; ++i)
#pragma unroll
                for (int j = 0; j < 8; ++j)
                    acc[i][j] = fmaf(a[i], b[j], acc[i][j]);
        }
        __syncthreads();
    }

    // --- epilogue: write proj (cols >= 200 dropped; float4 granularity clean) ---
#pragma unroll
    for (int ih = 0; ih < 2; ++ih)
#pragma unroll
    for (int i = 0; i < 4; ++i) {
        const int row = m0 + ih * 64 + (ty << 2) + i;
#pragma unroll
        for (int jh = 0; jh < 2; ++jh) {
            const int col = n0 + jh * 64 + (tx << 2);
            if (col < ROLE_D) {
                float4 v = make_float4(acc[ih * 4 + i][jh * 4 + 0],
                                       acc[ih * 4 + i][jh * 4 + 1],
                                       acc[ih * 4 + i][jh * 4 + 2],
                                       acc[ih * 4 + i][jh * 4 + 3]);
                *(float4*)(g_proj + (size_t)row * ROLE_D + col) = v;
            }
        }
    }
}

// ===========================================================================
// GEMM2 (batched): out[b*S+s, v] = proj[b,s,:] . roles[b,v,:], col 1 zeroed
// ===========================================================================
__global__ __launch_bounds__(256, 2) void score_kernel(
    const float* __restrict__ roles,   // [B, V*200]
    float* __restrict__ out,           // [B*S, V]
    int S, int V)
{
    __shared__ float As[KC][SSTR];   // [k][s]
    __shared__ float Bs[KC][SSTR];   // [k][v]

    const int t  = threadIdx.x;
    const int tx = t & 15;
    const int ty = t >> 4;
    const int b  = blockIdx.z;
    const int s0 = blockIdx.y * TS;
    const int v0 = blockIdx.x * TN;

    const float* Abase = g_proj + ((size_t)b * S + s0) * ROLE_D;
    const float* Bbase = roles + (size_t)b * V * ROLE_D;

    const int lrow = t >> 1;                 // 0..127
    const int lkq  = (t & 1) << 2;           // 0 or 4

    float acc[8][8] = {};

    const int nchunks = ROLE_D / KC;         // 25, exact
    for (int c = 0; c < nchunks; ++c) {
        const int k0 = c * KC;
        const int k  = k0 + lkq;
        // --- A tile (always in-bounds: S multiple of 128, K exact) ---
        {
            float4 v = *(const float4*)(Abase + (size_t)lrow * ROLE_D + k);
            As[lkq + 0][lrow] = v.x;
            As[lkq + 1][lrow] = v.y;
            As[lkq + 2][lrow] = v.z;
            As[lkq + 3][lrow] = v.w;
        }
        // --- B tile (roles, transposed; predicate v < V) ---
        {
            const int vrow = v0 + lrow;
            float4 v = make_float4(0.f, 0.f, 0.f, 0.f);
            if (vrow < V)
                v = *(const float4*)(Bbase + (size_t)vrow * ROLE_D + k);
            Bs[lkq + 0][lrow] = v.x;
            Bs[lkq + 1][lrow] = v.y;
            Bs[lkq + 2][lrow] = v.z;
            Bs[lkq + 3][lrow] = v.w;
        }
        __syncthreads();

#pragma unroll
        for (int kk = 0; kk < KC; ++kk) {
            const float4 a0 = *(const float4*)&As[kk][ty << 2];
            const float4 a1 = *(const float4*)&As[kk][64 + (ty << 2)];
            const float4 b0 = *(const float4*)&Bs[kk][tx << 2];
            const float4 b1 = *(const float4*)&Bs[kk][64 + (tx << 2)];
            const float a[8] = {a0.x, a0.y, a0.z, a0.w, a1.x, a1.y, a1.z, a1.w};
            const float bb[8] = {b0.x, b0.y, b0.z, b0.w, b1.x, b1.y, b1.z, b1.w};
#pragma unroll
            for (int i = 0; i < 8; ++i)
#pragma unroll
                for (int j = 0; j < 8; ++j)
                    acc[i][j] = fmaf(a[i], bb[j], acc[i][j]);
        }
        __syncthreads();
    }

    // --- epilogue: write scores, zero column v==1 ---
#pragma unroll
    for (int ih = 0; ih < 2; ++ih)
#pragma unroll
    for (int i = 0; i < 4; ++i) {
        const int s = s0 + ih * 64 + (ty << 2) + i;
        const size_t rbase = ((size_t)b * S + s) * (size_t)V;
#pragma unroll
        for (int jh = 0; jh < 2; ++jh) {
            const int vc = v0 + jh * 64 + (tx << 2);
            if (vc < V) {
                float4 v = make_float4(acc[ih * 4 + i][jh * 4 + 0],
                                       acc[ih * 4 + i][jh * 4 + 1],
                                       acc[ih * 4 + i][jh * 4 + 2],
                                       acc[ih * 4 + i][jh * 4 + 3]);
                if (vc == 0) v.y = 0.f;   // score column 1 forced to zero
                *(float4*)(out + rbase + vc) = v;
            }
        }
    }
}

// ===========================================================================
// kernel_launch
// inputs (metadata order): role_vectors, pretrained_emb, word_id_emb, matrix, seq_len
// ===========================================================================
extern "C" void kernel_launch(void* const* d_in, const int* in_sizes, int n_in,
                              void* d_out, int out_size)
{
    const float* roles = (const float*)d_in[0];
    const float* pre   = (const float*)d_in[1];
    const float* wid   = (const float*)d_in[2];
    const float* mat   = (const float*)d_in[3];

    const int BS = in_sizes[2] / FLAG;        // B*S
    const int S  = SEQ_S;                     // fixed by reference
    const int B  = BS / S;
    const int V  = in_sizes[0] / (B * ROLE_D);

    // GEMM1: proj
    dim3 g1((ROLE_D + TN - 1) / TN, BS / TS); // (2, 256)
    proj_kernel<<<g1, 256>>>(pre, wid, mat);

    // GEMM2: scores
    dim3 g2((V + TN - 1) / TN, S / TS, B);    // (3, 8, 32)
    score_kernel<<<g2, 256>>>(roles, (float*)d_out, S, V);
}

// round 3
// speedup vs baseline: 2.2466x; 2.2466x over previous
#include <cuda_runtime.h>
#include <cuda_fp16.h>
#include <cstdint>

#define DEVINL __device__ __forceinline__

namespace {
// problem constants
constexpr int Sn  = 1024;
constexpr int Vn  = 300;
constexpr int PRE = 300;
constexpr int FLG = 16;
constexpr int KQn = 316;
constexpr int RD  = 200;
constexpr int BSn = 32768;            // B*S

// tiling
constexpr int BM = 128, BN = 112, STR = 48;   // smem row stride in halves
constexpr int ASZ = BM * STR;                 // 6144 halves per split
constexpr int BSZ = BN * STR;                 // 5376
constexpr int AHo = 0, ALo = ASZ, BHo = 2 * ASZ, BLo = 2 * ASZ + BSZ;
constexpr int STAGE_H = 2 * ASZ + 2 * BSZ;    // 23040 halves = 46080 B
constexpr int SMEM_BYTES = 2 * STAGE_H * 2;   // 92160

constexpr int NC1 = 10;   // GEMM1 K chunks (K=316 -> 320)
constexpr int NC2 = 7;    // GEMM2 K chunks (K=200 -> 224)
constexpr int PW  = 224;  // proj padded width (k)
constexpr int RW  = 224;  // roles padded k
constexpr int RV  = 336;  // roles padded v
}

// fp16 hi/lo global scratch (allocation-free rule)
__device__ __half g_ph[(size_t)BSn * PW];
__device__ __half g_pl[(size_t)BSn * PW];
__device__ __half g_mh[224 * 320];
__device__ __half g_ml[224 * 320];
__device__ __half g_rh[(size_t)32 * RV * RW];
__device__ __half g_rl[(size_t)32 * RV * RW];

// ---------------------------------------------------------------------------
DEVINL uint32_t smem_u32(const void* p) {
    uint32_t a;
    asm("{ .reg .u64 t; cvta.to.shared.u64 t, %1; cvt.u32.u64 %0, t; }"
        : "=r"(a) : "l"(p));
    return a;
}
DEVINL void cp16(uint32_t dst, const void* src) {
    asm volatile("cp.async.cg.shared.global [%0], [%1], 16;"
                 :: "r"(dst), "l"(src) : "memory");
}
DEVINL void cp_commit() { asm volatile("cp.async.commit_group;" ::: "memory"); }
DEVINL void cp_wait0()  { asm volatile("cp.async.wait_group 0;" ::: "memory"); }

DEVINL void ldsm4(uint32_t a, uint32_t& r0, uint32_t& r1, uint32_t& r2, uint32_t& r3) {
    asm volatile("ldmatrix.sync.aligned.m8n8.x4.shared.b16 {%0,%1,%2,%3}, [%4];"
                 : "=r"(r0), "=r"(r1), "=r"(r2), "=r"(r3) : "r"(a));
}
DEVINL void ldsm2(uint32_t a, uint32_t& r0, uint32_t& r1) {
    asm volatile("ldmatrix.sync.aligned.m8n8.x2.shared.b16 {%0,%1}, [%2];"
                 : "=r"(r0), "=r"(r1) : "r"(a));
}
DEVINL void mma16816(float* c, const uint32_t* a, uint32_t b0, uint32_t b1) {
    asm volatile(
        "mma.sync.aligned.m16n8k16.row.col.f32.f16.f16.f32 "
        "{%0,%1,%2,%3}, {%4,%5,%6,%7}, {%8,%9}, {%0,%1,%2,%3};"
        : "+f"(c[0]), "+f"(c[1]), "+f"(c[2]), "+f"(c[3])
        : "r"(a[0]), "r"(a[1]), "r"(a[2]), "r"(a[3]), "r"(b0), "r"(b1));
}

// swizzle: flip 16B unit on row parity-of-4 (conflict-free ldmatrix at stride 96B)
DEVINL uint32_t swz(uint32_t byteoff, int row) { return byteoff ^ ((row & 4) << 2); }

DEVINL uint32_t packh(__half x, __half y) {
    return ((uint32_t)__half_as_ushort(y) << 16) | (uint32_t)__half_as_ushort(x);
}
// fp32 pair -> packed fp16 hi + fp16 residual
DEVINL void split2h(float x, float y, uint32_t& hi, uint32_t& lo) {
    __half hx = __float2half_rn(x), hy = __float2half_rn(y);
    __half lx = __float2half_rn(x - __half2float(hx));
    __half ly = __float2half_rn(y - __half2float(hy));
    hi = packh(hx, hy);
    lo = packh(lx, ly);
}
DEVINL void store_split_pair(__half* hp, __half* lp, size_t off, float x, float y) {
    uint32_t hi, lo;
    split2h(x, y, hi, lo);
    *reinterpret_cast<uint32_t*>(hp + off) = hi;
    *reinterpret_cast<uint32_t*>(lp + off) = lo;
}

// shared compute: one K-chunk (2 x k16 steps), warp tile 32x56
DEVINL void compute_chunk(uint32_t sb, int lane, int wm, int wn, float c[2][7][4]) {
    const int lr = lane & 15;
#pragma unroll
    for (int s = 0; s < 2; ++s) {
        uint32_t ah[2][4], al[2][4];
#pragma unroll
        for (int mi = 0; mi < 2; ++mi) {
            const int row = wm * 32 + mi * 16 + lr;
            const int col = s * 16 + (lane >> 4) * 8;
            const uint32_t off = swz((uint32_t)(row * STR + col) * 2, row);
            ldsm4(sb + AHo * 2 + off, ah[mi][0], ah[mi][1], ah[mi][2], ah[mi][3]);
            ldsm4(sb + ALo * 2 + off, al[mi][0], al[mi][1], al[mi][2], al[mi][3]);
        }
#pragma unroll
        for (int ni = 0; ni < 7; ++ni) {
            const int brow = wn * 56 + ni * 8 + (lr & 7);
            const int bcol = s * 16 + ((lr >> 3) & 1) * 8;
            const uint32_t boff = swz((uint32_t)(brow * STR + bcol) * 2, brow);
            uint32_t bh0, bh1, bl0, bl1;
            ldsm2(sb + BHo * 2 + boff, bh0, bh1);
            ldsm2(sb + BLo * 2 + boff, bl0, bl1);
#pragma unroll
            for (int mi = 0; mi < 2; ++mi) {
                mma16816(c[mi][ni], ah[mi], bh0, bh1);   // Ah*Bh
                mma16816(c[mi][ni], ah[mi], bl0, bl1);   // Ah*Bl
                mma16816(c[mi][ni], al[mi], bh0, bh1);   // Al*Bh
            }
        }
    }
}

// ===========================================================================
// prep kernels: split/pad into fp16 hi/lo scratch
// ===========================================================================
__global__ void prep_mat(const float* __restrict__ mat) {
    const int idx = blockIdx.x * 256 + threadIdx.x;    // 224*80 = 17920
    if (idx >= 224 * 80) return;
    const int n = idx / 80, k4 = (idx % 80) * 4;
#pragma unroll
    for (int i = 0; i < 4; ++i) {
        const int k = k4 + i;
        float v = 0.f;
        if (n < RD && k < KQn) v = mat[(size_t)k * RD + n];
        __half h = __float2half_rn(v);
        __half l = __float2half_rn(v - __half2float(h));
        g_mh[n * 320 + k] = h;
        g_ml[n * 320 + k] = l;
    }
}

__global__ void prep_roles(const float* __restrict__ roles) {
    const int idx = blockIdx.x * 256 + threadIdx.x;    // 32*336*56 = 602112
    if (idx >= 32 * RV * (RW / 4)) return;
    const int b  = idx / (RV * (RW / 4));
    const int r  = idx % (RV * (RW / 4));
    const int v  = r / (RW / 4);
    const int k  = (r % (RW / 4)) * 4;
    uint32_t h0 = 0, l0 = 0, h1 = 0, l1 = 0;
    if (v < Vn && k < RD) {
        const float4 f = *(const float4*)(roles + ((size_t)b * Vn + v) * RD + k);
        split2h(f.x, f.y, h0, l0);
        split2h(f.z, f.w, h1, l1);
    }
    const size_t off = (size_t)b * RV * RW + (size_t)v * RW + k;
    *reinterpret_cast<uint2*>(g_rh + off) = make_uint2(h0, h1);
    *reinterpret_cast<uint2*>(g_rl + off) = make_uint2(l0, l1);
}

// ===========================================================================
// GEMM1: proj(hi/lo f16)[BS,224] = concat(pre,wid)[BS,316] @ mat[316,200]
// ===========================================================================
__global__ __launch_bounds__(256, 2) void gemm1(
    const float* __restrict__ pre,
    const float* __restrict__ wid)
{
    extern __shared__ __align__(16) char smraw[];
    const uint32_t sb0 = smem_u32(smraw);
    const int t = threadIdx.x, lane = t & 31, warp = t >> 5;
    const int wm = warp >> 1, wn = warp & 1;
    const int m0 = blockIdx.x * BM;
    const int n0 = blockIdx.y * BN;

    float c[2][7][4] = {};
    float4 ar[4];

    auto ldA = [&](int ch) {
#pragma unroll
        for (int j = 0; j < 4; ++j) {
            const int idx = t + 256 * j;
            const int row = idx >> 3, c4 = idx & 7;
            const int kg = ch * 32 + c4 * 4;
            const size_t rg = (size_t)(m0 + row);
            float4 v = make_float4(0.f, 0.f, 0.f, 0.f);
            if (kg < PRE)      v = *(const float4*)(pre + rg * PRE + kg);
            else if (kg < KQn) v = *(const float4*)(wid + rg * FLG + (kg - PRE));
            ar[j] = v;
        }
    };
    auto stA = [&](uint32_t sb) {
#pragma unroll
        for (int j = 0; j < 4; ++j) {
            const int idx = t + 256 * j;
            const int row = idx >> 3, c4 = idx & 7;
            uint32_t h0, l0, h1, l1;
            split2h(ar[j].x, ar[j].y, h0, l0);
            split2h(ar[j].z, ar[j].w, h1, l1);
            const uint32_t off = swz((uint32_t)(row * 96 + c4 * 8), row);
            asm volatile("st.shared.v2.u32 [%0], {%1,%2};"
                         :: "r"(sb + AHo * 2 + off), "r"(h0), "r"(h1) : "memory");
            asm volatile("st.shared.v2.u32 [%0], {%1,%2};"
                         :: "r"(sb + ALo * 2 + off), "r"(l0), "r"(l1) : "memory");
        }
    };
    auto issueB = [&](int ch, uint32_t sb) {
#pragma unroll
        for (int j = 0; j < 4; ++j) {
            const int idx = t + 256 * j;
            if (idx < 896) {
                const int sp = idx / 448, rem = idx % 448;
                const int row = rem >> 2, c8 = rem & 3;
                const __half* src = (sp ? g_ml : g_mh)
                                  + (size_t)(n0 + row) * 320 + ch * 32 + c8 * 8;
                const uint32_t off = (sp ? BLo : BHo) * 2
                                   + swz((uint32_t)(row * 96 + c8 * 16), row);
                cp16(sb + off, src);
            }
        }
    };

    // preload chunk 0
    ldA(0);
    issueB(0, sb0);
    cp_commit();
    stA(sb0);
    cp_wait0();
    __syncthreads();

    for (int ch = 0; ch < NC1; ++ch) {
        const uint32_t cur = sb0 + (uint32_t)(ch & 1) * STAGE_H * 2;
        const uint32_t nxt = sb0 + (uint32_t)((ch + 1) & 1) * STAGE_H * 2;
        if (ch + 1 < NC1) { ldA(ch + 1); issueB(ch + 1, nxt); cp_commit(); }
        compute_chunk(cur, lane, wm, wn, c);
        if (ch + 1 < NC1) { stA(nxt); cp_wait0(); }
        __syncthreads();
    }

    // epilogue: split fp32 -> proj hi/lo f16 (cols >= 200 are exact zeros)
#pragma unroll
    for (int mi = 0; mi < 2; ++mi)
#pragma unroll
    for (int ni = 0; ni < 7; ++ni) {
        const int r0   = m0 + wm * 32 + mi * 16 + (lane >> 2);
        const int colg = n0 + wn * 56 + ni * 8 + (lane & 3) * 2;
        store_split_pair(g_ph, g_pl, (size_t)r0 * PW + colg,
                         c[mi][ni][0], c[mi][ni][1]);
        store_split_pair(g_ph, g_pl, (size_t)(r0 + 8) * PW + colg,
                         c[mi][ni][2], c[mi][ni][3]);
    }
}

// ===========================================================================
// GEMM2: out[r, v] = proj[r,:] . roles[b(r), v, :], col v==1 zeroed
// ===========================================================================
__global__ __launch_bounds__(256, 2) void gemm2(float* __restrict__ out)
{
    extern __shared__ __align__(16) char smraw[];
    const uint32_t sb0 = smem_u32(smraw);
    const int t = threadIdx.x, lane = t & 31, warp = t >> 5;
    const int wm = warp >> 1, wn = warp & 1;
    const int m0 = blockIdx.x * BM;
    const int n0 = blockIdx.y * BN;
    const int b  = blockIdx.x >> 3;           // 128-row tile within one batch

    float c[2][7][4] = {};
    const size_t rbase = (size_t)b * RV * RW;

    auto issue = [&](int ch, uint32_t sb) {
        const int k0 = ch * 32;
#pragma unroll
        for (int j = 0; j < 8; ++j) {
            const int idx = t + 256 * j;
            if (idx < 1024) {                       // A: proj hi/lo
                const int sp = idx >> 9, rem = idx & 511;
                const int row = rem >> 2, c8 = rem & 3;
                const __half* src = (sp ? g_pl : g_ph)
                                  + (size_t)(m0 + row) * PW + k0 + c8 * 8;
                const uint32_t off = (sp ? ALo : AHo) * 2
                                   + swz((uint32_t)(row * 96 + c8 * 16), row);
                cp16(sb + off, src);
            } else if (idx < 1920) {                // B: roles hi/lo
                const int i2 = idx - 1024;
                const int sp = i2 / 448, rem = i2 % 448;
                const int row = rem >> 2, c8 = rem & 3;
                const __half* src = (sp ? g_rl : g_rh)
                                  + rbase + (size_t)(n0 + row) * RW + k0 + c8 * 8;
                const uint32_t off = (sp ? BLo : BHo) * 2
                                   + swz((uint32_t)(row * 96 + c8 * 16), row);
                cp16(sb + off, src);
            }
        }
    };

    issue(0, sb0);
    cp_commit();
    cp_wait0();
    __syncthreads();

    for (int ch = 0; ch < NC2; ++ch) {
        const uint32_t cur = sb0 + (uint32_t)(ch & 1) * STAGE_H * 2;
        const uint32_t nxt = sb0 + (uint32_t)((ch + 1) & 1) * STAGE_H * 2;
        if (ch + 1 < NC2) { issue(ch + 1, nxt); cp_commit(); }
        compute_chunk(cur, lane, wm, wn, c);
        if (ch + 1 < NC2) cp_wait0();
        __syncthreads();
    }

    // epilogue: fp32 stores, zero global column 1
#pragma unroll
    for (int mi = 0; mi < 2; ++mi)
#pragma unroll
    for (int ni = 0; ni < 7; ++ni) {
        const int r0   = m0 + wm * 32 + mi * 16 + (lane >> 2);
        const int colg = n0 + wn * 56 + ni * 8 + (lane & 3) * 2;
        if (colg < Vn) {
            float a0 = c[mi][ni][0], a1 = c[mi][ni][1];
            float a2 = c[mi][ni][2], a3 = c[mi][ni][3];
            if (colg == 0) { a1 = 0.f; a3 = 0.f; }
            *(float2*)(out + (size_t)r0 * Vn + colg)       = make_float2(a0, a1);
            *(float2*)(out + (size_t)(r0 + 8) * Vn + colg) = make_float2(a2, a3);
        }
    }
}

// ===========================================================================
// kernel_launch  (inputs: role_vectors, pretrained_emb, word_id_emb, matrix, seq_len)
// ===========================================================================
extern "C" void kernel_launch(void* const* d_in, const int* in_sizes, int n_in,
                              void* d_out, int out_size)
{
    const float* roles = (const float*)d_in[0];
    const float* pre   = (const float*)d_in[1];
    const float* wid   = (const float*)d_in[2];
    const float* mat   = (const float*)d_in[3];

    cudaFuncSetAttribute(gemm1, cudaFuncAttributeMaxDynamicSharedMemorySize, SMEM_BYTES);
    cudaFuncSetAttribute(gemm2, cudaFuncAttributeMaxDynamicSharedMemorySize, SMEM_BYTES);

    prep_mat<<<(224 * 80 + 255) / 256, 256>>>(mat);
    prep_roles<<<(32 * RV * (RW / 4) + 255) / 256, 256>>>(roles);
    gemm1<<<dim3(BSn / BM, 2), 256, SMEM_BYTES>>>(pre, wid);
    gemm2<<<dim3(BSn / BM, 3), 256, SMEM_BYTES>>>((float*)d_out);
}